// round 2
// baseline (speedup 1.0000x reference)
#include <cuda_runtime.h>
#include <cuda_bf16.h>
#include <cstdint>

// LogicLayer: y[n, j] = c0[j] + c1[j]*a + c2[j]*b + c3[j]*a*b
//   (c0..c3) = softmax(weights[j,:16]) @ GATE_COEFS
//   a = x[n, idx_a[j]], b = x[n, idx_b[j]]
// x: [16384, 4096] f32, weights: [4096,16] f32, idx_a/idx_b: [4096] (int32 OR int64 — detected at runtime)
// out: [16384, 4096] f32

#define IN_DIM   4096
#define OUT_DIM  4096
#define BATCH    16384
#define ROWS     4          // rows per block
#define THREADS  256

__device__ float4 g_coef[OUT_DIM];
__device__ int2   g_idx [OUT_DIM];

// GATE_COEFS columns (c0,c1,c2,c3) per gate index 0..15
__constant__ float G0[16] = {0,0,0,0, 0,0,0,0, 1,1,1,1, 1,1,1,1};
__constant__ float G1[16] = {0,0,1,1, 0,0,1,1, -1,-1,0,0, -1,-1,0,0};
__constant__ float G2[16] = {0,0,0,0, 1,1,1,1, -1,-1,-1,-1, 0,0,0,0};
__constant__ float G3[16] = {0,1,-1,0, -1,0,-2,-1, 1,2,0,1, 0,1,-1,0};

// Detect whether an index buffer (4096 logical elements, values in [0,4096))
// is stored as int64 (little-endian: odd int32 words all zero) or int32.
__device__ __forceinline__ bool idx_is_i64(const int* p)
{
    bool i64 = true;
    #pragma unroll
    for (int i = 0; i < 16; ++i) {
        int lo = p[2 * i];
        int hi = p[2 * i + 1];
        if (hi != 0 || (unsigned)lo >= IN_DIM) { i64 = false; break; }
    }
    return i64;
}

__device__ __forceinline__ int load_idx(const int* p, bool i64, int j)
{
    int v = i64 ? p[2 * j] : p[j];
    // defensive clamp
    return (v < 0) ? 0 : (v >= IN_DIM ? IN_DIM - 1 : v);
}

__global__ void precompute_kernel(const float* __restrict__ w,
                                  const int* __restrict__ ia,
                                  const int* __restrict__ ib)
{
    int j = blockIdx.x * blockDim.x + threadIdx.x;
    if (j >= OUT_DIM) return;

    const bool a64 = idx_is_i64(ia);
    const bool b64 = idx_is_i64(ib);

    const float* wr = w + j * 16;
    float wv[16];
    float m = -1e30f;
    #pragma unroll
    for (int i = 0; i < 16; ++i) { wv[i] = wr[i]; m = fmaxf(m, wv[i]); }
    float s = 0.f;
    #pragma unroll
    for (int i = 0; i < 16; ++i) { wv[i] = expf(wv[i] - m); s += wv[i]; }
    float inv = 1.0f / s;
    float c0 = 0.f, c1 = 0.f, c2 = 0.f, c3 = 0.f;
    #pragma unroll
    for (int i = 0; i < 16; ++i) {
        float p = wv[i] * inv;
        c0 = fmaf(p, G0[i], c0);
        c1 = fmaf(p, G1[i], c1);
        c2 = fmaf(p, G2[i], c2);
        c3 = fmaf(p, G3[i], c3);
    }
    g_coef[j] = make_float4(c0, c1, c2, c3);
    g_idx[j]  = make_int2(load_idx(ia, a64, j), load_idx(ib, b64, j));
}

// Main kernel: each block processes ROWS=4 rows, all 4096 outputs.
// smem: x tile transposed, xs[c*ROWS + r]  (64 KB dynamic)
__global__ __launch_bounds__(THREADS)
void logic_main_kernel(const float* __restrict__ x, float* __restrict__ y)
{
    extern __shared__ float xs[];   // IN_DIM * ROWS floats

    const int row0 = blockIdx.x * ROWS;
    const int t    = threadIdx.x;
    const int lane = t & 31;
    const int warp = t >> 5;        // 8 warps

    // ---- stage: load 4 rows, transposed, conflict-free STS ----
    // lane l: row r = l%4, column-group cg = l/4 (0..7)
    {
        const int r  = lane & 3;
        const int cg = lane >> 2;
        const float* xrow = x + (size_t)(row0 + r) * IN_DIM;
        const int cbeg = warp * (IN_DIM / 8);      // 512 columns per warp
        #pragma unroll 4
        for (int base = cbeg; base < cbeg + (IN_DIM / 8); base += 8) {
            int c = base + cg;
            xs[c * ROWS + r] = xrow[c];
        }
    }
    __syncthreads();

    const float4* __restrict__ xs4 = (const float4*)xs;  // xs4[c] = rows 0..3 of column c

    // ---- compute: each thread owns 4 consecutive j's per iteration ----
    #pragma unroll 1
    for (int iter = 0; iter < OUT_DIM / (THREADS * 4); ++iter) {
        const int j0 = iter * (THREADS * 4) + t * 4;

        float out[ROWS][4];
        #pragma unroll
        for (int k = 0; k < 4; ++k) {
            const int j = j0 + k;
            const float4 cf = g_coef[j];
            const int2  ij  = g_idx[j];
            const float4 a = xs4[ij.x];
            const float4 b = xs4[ij.y];
            // y = (c0 + c1*a) + b*(c2 + c3*a)   -> 3 FMA per element
            out[0][k] = fmaf(b.x, fmaf(cf.w, a.x, cf.z), fmaf(cf.y, a.x, cf.x));
            out[1][k] = fmaf(b.y, fmaf(cf.w, a.y, cf.z), fmaf(cf.y, a.y, cf.x));
            out[2][k] = fmaf(b.z, fmaf(cf.w, a.z, cf.z), fmaf(cf.y, a.z, cf.x));
            out[3][k] = fmaf(b.w, fmaf(cf.w, a.w, cf.z), fmaf(cf.y, a.w, cf.x));
        }

        #pragma unroll
        for (int r = 0; r < ROWS; ++r) {
            float4 v = make_float4(out[r][0], out[r][1], out[r][2], out[r][3]);
            float4* yrow = (float4*)(y + (size_t)(row0 + r) * OUT_DIM);
            yrow[j0 >> 2] = v;
        }
    }
}

extern "C" void kernel_launch(void* const* d_in, const int* in_sizes, int n_in,
                              void* d_out, int out_size)
{
    const float* x  = (const float*)d_in[0];
    const float* w  = (const float*)d_in[1];
    const int*   ia = (const int*)d_in[2];
    const int*   ib = (const int*)d_in[3];
    float*       y  = (float*)d_out;

    cudaFuncSetAttribute(logic_main_kernel,
                         cudaFuncAttributeMaxDynamicSharedMemorySize,
                         IN_DIM * ROWS * (int)sizeof(float));

    precompute_kernel<<<(OUT_DIM + 255) / 256, 256>>>(w, ia, ib);

    const int smem = IN_DIM * ROWS * (int)sizeof(float);
    logic_main_kernel<<<BATCH / ROWS, THREADS, smem>>>(x, y);
}